// round 1
// baseline (speedup 1.0000x reference)
#include <cuda_runtime.h>
#include <math.h>

#define HIDDEN  1024
#define NH      16
#define HD      64
#define SEQ     2048
#define BATCH   2
#define BTOK    (BATCH * SEQ)      // 4096 rows
#define QKVCOLS (3 * HIDDEN)       // 3072

// Scratch (allocation-free rule: __device__ globals)
__device__ float g_qkv[(size_t)BTOK * QKVCOLS];   // [4096, 3072]
__device__ float g_ctx[(size_t)BTOK * HIDDEN];    // [4096, 1024]

// ---------------------------------------------------------------------------
// SGEMM: C[M,N] = A[M,K] @ B[N,K]^T   (A row-major, B row-major weight layout)
// Tile 128x128x16, 256 threads, 8x8 per-thread microtile.
// Dims are guaranteed multiples of the tile sizes for this problem.
// ---------------------------------------------------------------------------
__global__ __launch_bounds__(256, 2)
void sgemm_tn(const float* __restrict__ A, const float* __restrict__ B,
              float* __restrict__ C, int M, int N, int K)
{
    __shared__ float As[16][132];   // [k][m], padded
    __shared__ float Bs[16][132];   // [k][n], padded

    const int tid = threadIdx.x;
    const int tm  = tid >> 4;       // 0..15
    const int tn  = tid & 15;       // 0..15
    const int m0  = blockIdx.y * 128;
    const int n0  = blockIdx.x * 128;

    float acc[8][8];
#pragma unroll
    for (int i = 0; i < 8; i++)
#pragma unroll
        for (int j = 0; j < 8; j++) acc[i][j] = 0.f;

    for (int k0 = 0; k0 < K; k0 += 16) {
        // Load A tile (128x16) transposed into As[k][m]
#pragma unroll
        for (int p = 0; p < 2; p++) {
            int t = tid + p * 256;           // 0..511
            int r = t >> 2;                  // 0..127
            int c = (t & 3) << 2;            // 0,4,8,12
            float4 v = *(const float4*)&A[(size_t)(m0 + r) * K + k0 + c];
            As[c + 0][r] = v.x; As[c + 1][r] = v.y;
            As[c + 2][r] = v.z; As[c + 3][r] = v.w;
        }
        // Load B tile (128x16) transposed into Bs[k][n]
#pragma unroll
        for (int p = 0; p < 2; p++) {
            int t = tid + p * 256;
            int r = t >> 2;
            int c = (t & 3) << 2;
            float4 v = *(const float4*)&B[(size_t)(n0 + r) * K + k0 + c];
            Bs[c + 0][r] = v.x; Bs[c + 1][r] = v.y;
            Bs[c + 2][r] = v.z; Bs[c + 3][r] = v.w;
        }
        __syncthreads();

#pragma unroll
        for (int kk = 0; kk < 16; kk++) {
            float a[8], b[8];
            *(float4*)&a[0] = *(const float4*)&As[kk][tm * 8];
            *(float4*)&a[4] = *(const float4*)&As[kk][tm * 8 + 4];
            *(float4*)&b[0] = *(const float4*)&Bs[kk][tn * 8];
            *(float4*)&b[4] = *(const float4*)&Bs[kk][tn * 8 + 4];
#pragma unroll
            for (int i = 0; i < 8; i++)
#pragma unroll
                for (int j = 0; j < 8; j++)
                    acc[i][j] = fmaf(a[i], b[j], acc[i][j]);
        }
        __syncthreads();
    }

#pragma unroll
    for (int i = 0; i < 8; i++) {
        size_t row = (size_t)(m0 + tm * 8 + i) * N + n0 + tn * 8;
        float4 v0 = make_float4(acc[i][0], acc[i][1], acc[i][2], acc[i][3]);
        float4 v1 = make_float4(acc[i][4], acc[i][5], acc[i][6], acc[i][7]);
        *(float4*)&C[row]     = v0;
        *(float4*)&C[row + 4] = v1;
    }
}

// ---------------------------------------------------------------------------
// Flash attention (fp32, online softmax).
// Grid: (S/64, B*H). Block: 256 threads. Each block: 64 q-rows of one (b,h).
// smem: Qt[64][68] (d-major), Kt[64][68] (d-major, reused as Pt[k][m]),
//       Vs[64][68] (k-major). Per-thread 4x4 microtile: tx=col group, ty=row.
// ---------------------------------------------------------------------------
#define ASTRIDE 68
#define ASMEM_BYTES (3 * 64 * ASTRIDE * 4)

__global__ __launch_bounds__(256, 4)
void attn_kernel(const float* __restrict__ qkv, float* __restrict__ ctx)
{
    extern __shared__ float sm[];
    float (*Qt)[ASTRIDE] = (float(*)[ASTRIDE])(sm);
    float (*Kt)[ASTRIDE] = (float(*)[ASTRIDE])(sm + 64 * ASTRIDE);      // also Pt
    float (*Vs)[ASTRIDE] = (float(*)[ASTRIDE])(sm + 2 * 64 * ASTRIDE);

    const int tid = threadIdx.x;
    const int tx  = tid & 15;     // col group (0..15)
    const int ty  = tid >> 4;     // row group (0..15)
    const int q0  = blockIdx.x * 64;
    const int bh  = blockIdx.y;
    const int b   = bh / NH;
    const int h   = bh % NH;
    const size_t rowbase = (size_t)b * SEQ;
    const float scale = 0.125f;   // 1/sqrt(64)

    // Load Q tile transposed: Qt[d][m]
#pragma unroll
    for (int p = 0; p < 4; p++) {
        int t = tid + p * 256;          // 0..1023
        int r = t >> 4;                 // q row 0..63
        int c = (t & 15) << 2;          // d 0..60
        float4 v = *(const float4*)&qkv[(rowbase + q0 + r) * QKVCOLS + h * HD + c];
        Qt[c + 0][r] = v.x; Qt[c + 1][r] = v.y;
        Qt[c + 2][r] = v.z; Qt[c + 3][r] = v.w;
    }

    float m[4], l[4], acc[4][4];
#pragma unroll
    for (int i = 0; i < 4; i++) {
        m[i] = -1e30f; l[i] = 0.f;
#pragma unroll
        for (int j = 0; j < 4; j++) acc[i][j] = 0.f;
    }

    for (int kv0 = 0; kv0 < SEQ; kv0 += 64) {
        // Load K (transposed -> Kt[d][n]) and V (k-major -> Vs[k][n])
#pragma unroll
        for (int p = 0; p < 4; p++) {
            int t = tid + p * 256;
            int r = t >> 4;
            int c = (t & 15) << 2;
            const float* base = &qkv[(rowbase + kv0 + r) * QKVCOLS + h * HD + c];
            float4 kv = *(const float4*)(base + HIDDEN);       // K block
            Kt[c + 0][r] = kv.x; Kt[c + 1][r] = kv.y;
            Kt[c + 2][r] = kv.z; Kt[c + 3][r] = kv.w;
            float4 vv = *(const float4*)(base + 2 * HIDDEN);   // V block
            *(float4*)&Vs[r][c] = vv;
        }
        __syncthreads();

        // S = scale * Q @ K^T  (4x4 microtile)
        float s[4][4];
#pragma unroll
        for (int i = 0; i < 4; i++)
#pragma unroll
            for (int j = 0; j < 4; j++) s[i][j] = 0.f;

#pragma unroll 4
        for (int d = 0; d < 64; d++) {
            float4 q4 = *(const float4*)&Qt[d][ty * 4];
            float4 k4 = *(const float4*)&Kt[d][tx * 4];
            float qa[4] = {q4.x, q4.y, q4.z, q4.w};
            float kb[4] = {k4.x, k4.y, k4.z, k4.w};
#pragma unroll
            for (int i = 0; i < 4; i++)
#pragma unroll
                for (int j = 0; j < 4; j++)
                    s[i][j] = fmaf(qa[i], kb[j], s[i][j]);
        }

        // Online softmax: row-wise over 16 tx-threads (width-16 shuffles)
        float p[4][4], alpha[4];
#pragma unroll
        for (int i = 0; i < 4; i++) {
            float rm = -1e30f;
#pragma unroll
            for (int j = 0; j < 4; j++) {
                s[i][j] *= scale;
                rm = fmaxf(rm, s[i][j]);
            }
#pragma unroll
            for (int off = 8; off >= 1; off >>= 1)
                rm = fmaxf(rm, __shfl_xor_sync(0xffffffffu, rm, off, 16));
            float mn = fmaxf(m[i], rm);
            alpha[i] = __expf(m[i] - mn);
            m[i] = mn;
            float rs = 0.f;
#pragma unroll
            for (int j = 0; j < 4; j++) {
                p[i][j] = __expf(s[i][j] - mn);
                rs += p[i][j];
            }
#pragma unroll
            for (int off = 8; off >= 1; off >>= 1)
                rs += __shfl_xor_sync(0xffffffffu, rs, off, 16);
            l[i] = l[i] * alpha[i] + rs;
#pragma unroll
            for (int j = 0; j < 4; j++) acc[i][j] *= alpha[i];
        }

        __syncthreads();   // all done reading Kt -> safe to overwrite with P

        // Store P transposed into Kt: Pt[k][m]
#pragma unroll
        for (int j = 0; j < 4; j++)
#pragma unroll
            for (int i = 0; i < 4; i++)
                Kt[tx * 4 + j][ty * 4 + i] = p[i][j];
        __syncthreads();

        // O += P @ V
#pragma unroll 4
        for (int k = 0; k < 64; k++) {
            float4 p4 = *(const float4*)&Kt[k][ty * 4];
            float4 v4 = *(const float4*)&Vs[k][tx * 4];
            float pa[4] = {p4.x, p4.y, p4.z, p4.w};
            float vb[4] = {v4.x, v4.y, v4.z, v4.w};
#pragma unroll
            for (int i = 0; i < 4; i++)
#pragma unroll
                for (int j = 0; j < 4; j++)
                    acc[i][j] = fmaf(pa[i], vb[j], acc[i][j]);
        }
        __syncthreads();   // before next chunk overwrites Kt/Vs
    }

    // Normalize and write ctx[b, s, h*64 + d]
#pragma unroll
    for (int i = 0; i < 4; i++) {
        float inv = 1.f / l[i];
        float4 o = make_float4(acc[i][0] * inv, acc[i][1] * inv,
                               acc[i][2] * inv, acc[i][3] * inv);
        size_t idx = (rowbase + q0 + ty * 4 + i) * HIDDEN + h * HD + tx * 4;
        *(float4*)&ctx[idx] = o;
    }
}

// ---------------------------------------------------------------------------
extern "C" void kernel_launch(void* const* d_in, const int* in_sizes, int n_in,
                              void* d_out, int out_size)
{
    const float* x       = (const float*)d_in[0];   // [2,2048,1024]
    const float* w_qkv   = (const float*)d_in[1];   // [3072,1024]
    const float* w_dense = (const float*)d_in[2];   // [1024,1024]
    float* out           = (float*)d_out;           // [2,2048,1024]

    float* qkv; float* ctx;
    cudaGetSymbolAddress((void**)&qkv, g_qkv);
    cudaGetSymbolAddress((void**)&ctx, g_ctx);

    // 1) QKV projection: g_qkv[4096,3072] = x[4096,1024] @ w_qkv^T
    {
        dim3 grid(QKVCOLS / 128, BTOK / 128);
        sgemm_tn<<<grid, 256>>>(x, w_qkv, qkv, BTOK, QKVCOLS, HIDDEN);
    }

    // 2) Attention: g_ctx[4096,1024]
    {
        cudaFuncSetAttribute(attn_kernel,
                             cudaFuncAttributeMaxDynamicSharedMemorySize,
                             ASMEM_BYTES);
        dim3 grid(SEQ / 64, BATCH * NH);
        attn_kernel<<<grid, 256, ASMEM_BYTES>>>(qkv, ctx);
    }

    // 3) Output dense: out[4096,1024] = ctx @ w_dense^T
    {
        dim3 grid(HIDDEN / 128, BTOK / 128);
        sgemm_tn<<<grid, 256>>>(ctx, w_dense, out, BTOK, HIDDEN, HIDDEN);
    }
}

// round 4
// speedup vs baseline: 1.2077x; 1.2077x over previous
#include <cuda_runtime.h>
#include <cuda_bf16.h>
#include <math.h>
#include <stdint.h>

#define HIDDEN  1024
#define NH      16
#define HD      64
#define SEQ     2048
#define BATCH   2
#define BTOK    (BATCH * SEQ)      // 4096 rows
#define QKVCOLS (3 * HIDDEN)       // 3072

// ---------------------------------------------------------------------------
// Device-global scratch (allocation-free rule)
// ---------------------------------------------------------------------------
__device__ float g_qkv[(size_t)BTOK * QKVCOLS];                 // [4096,3072] fp32

__device__ __nv_bfloat16 g_x_hi[(size_t)BTOK * HIDDEN];
__device__ __nv_bfloat16 g_x_lo[(size_t)BTOK * HIDDEN];
__device__ __nv_bfloat16 g_wq_hi[(size_t)QKVCOLS * HIDDEN];
__device__ __nv_bfloat16 g_wq_lo[(size_t)QKVCOLS * HIDDEN];
__device__ __nv_bfloat16 g_wd_hi[(size_t)HIDDEN * HIDDEN];
__device__ __nv_bfloat16 g_wd_lo[(size_t)HIDDEN * HIDDEN];
__device__ __nv_bfloat16 g_ctx_hi[(size_t)BTOK * HIDDEN];
__device__ __nv_bfloat16 g_ctx_lo[(size_t)BTOK * HIDDEN];

// ---------------------------------------------------------------------------
// fp32 -> (bf16 hi, bf16 lo) conversion
// ---------------------------------------------------------------------------
__global__ void cvt_hilo(const float* __restrict__ in,
                         __nv_bfloat16* __restrict__ hi,
                         __nv_bfloat16* __restrict__ lo, int n4)
{
    int i = blockIdx.x * blockDim.x + threadIdx.x;
    if (i >= n4) return;
    float4 v = *(const float4*)&in[i * 4];
    __nv_bfloat162 h01 = __floats2bfloat162_rn(v.x, v.y);
    __nv_bfloat162 h23 = __floats2bfloat162_rn(v.z, v.w);
    __nv_bfloat162 l01 = __floats2bfloat162_rn(v.x - __bfloat162float(h01.x),
                                               v.y - __bfloat162float(h01.y));
    __nv_bfloat162 l23 = __floats2bfloat162_rn(v.z - __bfloat162float(h23.x),
                                               v.w - __bfloat162float(h23.y));
    *(uint2*)&hi[i * 4] = make_uint2(*(uint32_t*)&h01, *(uint32_t*)&h23);
    *(uint2*)&lo[i * 4] = make_uint2(*(uint32_t*)&l01, *(uint32_t*)&l23);
}

// ---------------------------------------------------------------------------
// PTX wrappers (sm_80-class, legal on compute_103)
// ---------------------------------------------------------------------------
__device__ __forceinline__ uint32_t smem_u32(const void* p) {
    uint32_t a;
    asm("{ .reg .u64 t; cvta.to.shared.u64 t, %1; cvt.u32.u64 %0, t; }"
        : "=r"(a) : "l"(p));
    return a;
}

__device__ __forceinline__ void ldm_x4(uint32_t* r, uint32_t addr) {
    asm volatile("ldmatrix.sync.aligned.m8n8.x4.shared.b16 {%0,%1,%2,%3}, [%4];"
                 : "=r"(r[0]), "=r"(r[1]), "=r"(r[2]), "=r"(r[3]) : "r"(addr));
}

__device__ __forceinline__ void mma16816(float* d, const uint32_t* a,
                                         uint32_t b0, uint32_t b1) {
    asm volatile(
        "mma.sync.aligned.m16n8k16.row.col.f32.bf16.bf16.f32 "
        "{%0,%1,%2,%3}, {%4,%5,%6,%7}, {%8,%9}, {%0,%1,%2,%3};"
        : "+f"(d[0]), "+f"(d[1]), "+f"(d[2]), "+f"(d[3])
        : "r"(a[0]), "r"(a[1]), "r"(a[2]), "r"(a[3]), "r"(b0), "r"(b1));
}

__device__ __forceinline__ void cp_async16(uint32_t dst, const void* src) {
    asm volatile("cp.async.cg.shared.global [%0], [%1], 16;"
                 :: "r"(dst), "l"(src));
}
#define CP_COMMIT() asm volatile("cp.async.commit_group;")
#define CP_WAIT(N)  asm volatile("cp.async.wait_group %0;" :: "n"(N))

// ===========================================================================
// bf16 split-precision GEMM: C[M,N] = A[M,K] @ B[N,K]^T (hi/lo bf16 in, f32 out)
// Block 128x128, BK=64, 256 threads (8 warps as 2m x 4n, warp tile 64x32).
// Double-buffered cp.async. Row stride 72 bf16 (144B) -> conflict-free ldmatrix.
// ===========================================================================
#define BK 64
#define STRD 72                       // bf16 elements per smem row
#define ATILE_B (128 * STRD * 2)      // bytes per tile (18432)
#define GBUF_B  (4 * ATILE_B)         // Ahi,Alo,Bhi,Blo (73728)
#define GSMEM_B (2 * GBUF_B)          // double buffer (147456)

__global__ __launch_bounds__(256)
void gemm_bf16(const __nv_bfloat16* __restrict__ Ahi,
               const __nv_bfloat16* __restrict__ Alo,
               const __nv_bfloat16* __restrict__ Bhi,
               const __nv_bfloat16* __restrict__ Blo,
               float* __restrict__ C, int N, int K)
{
    extern __shared__ char sm[];
    const uint32_t smb = smem_u32(sm);
    const int tid = threadIdx.x;
    const int wid = tid >> 5;
    const int lane = tid & 31;
    const int wm = wid & 1;           // 0..1 -> m offset 64
    const int wn = wid >> 1;          // 0..3 -> n offset 32
    const int n0 = blockIdx.x * 128;
    const int m0 = blockIdx.y * 128;

    // cp.async source/dest indexing: 16B chunks. Per tile: 128 rows x 8 chunks.
    const int cr = tid >> 1;                 // row 0..127 (2 threads/row)
    const int cc = (tid & 1) << 5;           // col 0 or 32 (bf16 units), 4 chunks each
    const size_t gA = (size_t)(m0 + cr) * K + cc;
    const size_t gB = (size_t)(n0 + cr) * K + cc;
    const uint32_t sRow = (uint32_t)(cr * STRD + cc) * 2;  // byte offset in tile

    float acc[4][4][4];
#pragma unroll
    for (int i = 0; i < 4; i++)
#pragma unroll
        for (int j = 0; j < 4; j++)
#pragma unroll
            for (int f = 0; f < 4; f++) acc[i][j][f] = 0.f;

    // ldmatrix per-lane base offsets (bytes within a tile)
    const uint32_t aoff = ((wm * 64 + (lane & 15)) * STRD + ((lane >> 4) << 3)) * 2;
    const uint32_t boff = ((wn * 32 + (lane & 15)) * STRD + ((lane >> 4) << 3)) * 2;

    const int nch = K >> 6;

    // ---- issue one chunk's 4 tiles via cp.async ----
    auto issue = [&](int buf, int k0) {
        uint32_t base = smb + buf * GBUF_B;
#pragma unroll
        for (int q = 0; q < 4; q++) {       // 4 x 16B = 64B = 32 bf16 per thread/tile
            uint32_t so = sRow + q * 16;
            int go = k0 + q * 8;
            cp_async16(base + 0 * ATILE_B + so, Ahi + gA + go);
            cp_async16(base + 1 * ATILE_B + so, Alo + gA + go);
            cp_async16(base + 2 * ATILE_B + so, Bhi + gB + go);
            cp_async16(base + 3 * ATILE_B + so, Blo + gB + go);
        }
        CP_COMMIT();
    };

    issue(0, 0);

    for (int ch = 0; ch < nch; ch++) {
        const int buf = ch & 1;
        if (ch + 1 < nch) { issue(1 - buf, (ch + 1) << 6); CP_WAIT(1); }
        else              { CP_WAIT(0); }
        __syncthreads();

        const uint32_t tAhi = smb + buf * GBUF_B;
        const uint32_t tAlo = tAhi + ATILE_B;
        const uint32_t tBhi = tAhi + 2 * ATILE_B;
        const uint32_t tBlo = tAhi + 3 * ATILE_B;

#pragma unroll
        for (int kk = 0; kk < 4; kk++) {
            const uint32_t ko = kk * 16 * 2;   // byte col offset
            uint32_t ah[4][4], bh[2][4];
#pragma unroll
            for (int mi = 0; mi < 4; mi++)
                ldm_x4(ah[mi], tAhi + aoff + mi * (16 * STRD * 2) + ko);
#pragma unroll
            for (int nt = 0; nt < 2; nt++)
                ldm_x4(bh[nt], tBhi + boff + nt * (16 * STRD * 2) + ko);
            // hi * hi
#pragma unroll
            for (int mi = 0; mi < 4; mi++)
#pragma unroll
                for (int nt = 0; nt < 2; nt++)
#pragma unroll
                    for (int h = 0; h < 2; h++)
                        mma16816(acc[mi][nt * 2 + h], ah[mi], bh[nt][h], bh[nt][h + 2]);
            // hi * lo
            {
                uint32_t bl[2][4];
#pragma unroll
                for (int nt = 0; nt < 2; nt++)
                    ldm_x4(bl[nt], tBlo + boff + nt * (16 * STRD * 2) + ko);
#pragma unroll
                for (int mi = 0; mi < 4; mi++)
#pragma unroll
                    for (int nt = 0; nt < 2; nt++)
#pragma unroll
                        for (int h = 0; h < 2; h++)
                            mma16816(acc[mi][nt * 2 + h], ah[mi], bl[nt][h], bl[nt][h + 2]);
            }
            // lo * hi
            {
                uint32_t al[4][4];
#pragma unroll
                for (int mi = 0; mi < 4; mi++)
                    ldm_x4(al[mi], tAlo + aoff + mi * (16 * STRD * 2) + ko);
#pragma unroll
                for (int mi = 0; mi < 4; mi++)
#pragma unroll
                    for (int nt = 0; nt < 2; nt++)
#pragma unroll
                        for (int h = 0; h < 2; h++)
                            mma16816(acc[mi][nt * 2 + h], al[mi], bh[nt][h], bh[nt][h + 2]);
            }
        }
        __syncthreads();
    }

    // Epilogue: fragment layout c0,c1=(m, n..n+1), c2,c3=(m+8, n..n+1)
    const int mrow = m0 + wm * 64 + (lane >> 2);
    const int ncol = n0 + wn * 32 + (lane & 3) * 2;
#pragma unroll
    for (int mi = 0; mi < 4; mi++)
#pragma unroll
        for (int nj = 0; nj < 4; nj++) {
            float* d = acc[mi][nj];
            size_t r0 = (size_t)(mrow + mi * 16) * N + ncol + nj * 8;
            size_t r1 = r0 + 8 * (size_t)N;
            *(float2*)&C[r0] = make_float2(d[0], d[1]);
            *(float2*)&C[r1] = make_float2(d[2], d[3]);
        }
}

// ---------------------------------------------------------------------------
// Flash attention (fp32, online softmax). Epilogue writes ctx as hi/lo bf16.
// ---------------------------------------------------------------------------
#define ASTRIDE 68
#define ASMEM_BYTES (3 * 64 * ASTRIDE * 4)

__global__ __launch_bounds__(256, 4)
void attn_kernel(const float* __restrict__ qkv,
                 __nv_bfloat16* __restrict__ ctx_hi,
                 __nv_bfloat16* __restrict__ ctx_lo)
{
    extern __shared__ float smf[];
    float (*Qt)[ASTRIDE] = (float(*)[ASTRIDE])(smf);
    float (*Kt)[ASTRIDE] = (float(*)[ASTRIDE])(smf + 64 * ASTRIDE);
    float (*Vs)[ASTRIDE] = (float(*)[ASTRIDE])(smf + 2 * 64 * ASTRIDE);

    const int tid = threadIdx.x;
    const int tx  = tid & 15;
    const int ty  = tid >> 4;
    const int q0  = blockIdx.x * 64;
    const int bh  = blockIdx.y;
    const int b   = bh / NH;
    const int h   = bh % NH;
    const size_t rowbase = (size_t)b * SEQ;
    const float scale = 0.125f;

#pragma unroll
    for (int p = 0; p < 4; p++) {
        int t = tid + p * 256;
        int r = t >> 4;
        int c = (t & 15) << 2;
        float4 v = *(const float4*)&qkv[(rowbase + q0 + r) * QKVCOLS + h * HD + c];
        Qt[c + 0][r] = v.x; Qt[c + 1][r] = v.y;
        Qt[c + 2][r] = v.z; Qt[c + 3][r] = v.w;
    }

    float m[4], l[4], acc[4][4];
#pragma unroll
    for (int i = 0; i < 4; i++) {
        m[i] = -1e30f; l[i] = 0.f;
#pragma unroll
        for (int j = 0; j < 4; j++) acc[i][j] = 0.f;
    }

    for (int kv0 = 0; kv0 < SEQ; kv0 += 64) {
#pragma unroll
        for (int p = 0; p < 4; p++) {
            int t = tid + p * 256;
            int r = t >> 4;
            int c = (t & 15) << 2;
            const float* base = &qkv[(rowbase + kv0 + r) * QKVCOLS + h * HD + c];
            float4 kv = *(const float4*)(base + HIDDEN);
            Kt[c + 0][r] = kv.x; Kt[c + 1][r] = kv.y;
            Kt[c + 2][r] = kv.z; Kt[c + 3][r] = kv.w;
            float4 vv = *(const float4*)(base + 2 * HIDDEN);
            *(float4*)&Vs[r][c] = vv;
        }
        __syncthreads();

        float s[4][4];
#pragma unroll
        for (int i = 0; i < 4; i++)
#pragma unroll
            for (int j = 0; j < 4; j++) s[i][j] = 0.f;

#pragma unroll 4
        for (int d = 0; d < 64; d++) {
            float4 q4 = *(const float4*)&Qt[d][ty * 4];
            float4 k4 = *(const float4*)&Kt[d][tx * 4];
            float qa[4] = {q4.x, q4.y, q4.z, q4.w};
            float kb[4] = {k4.x, k4.y, k4.z, k4.w};
#pragma unroll
            for (int i = 0; i < 4; i++)
#pragma unroll
                for (int j = 0; j < 4; j++)
                    s[i][j] = fmaf(qa[i], kb[j], s[i][j]);
        }

        float p[4][4], alpha[4];
#pragma unroll
        for (int i = 0; i < 4; i++) {
            float rm = -1e30f;
#pragma unroll
            for (int j = 0; j < 4; j++) {
                s[i][j] *= scale;
                rm = fmaxf(rm, s[i][j]);
            }
#pragma unroll
            for (int off = 8; off >= 1; off >>= 1)
                rm = fmaxf(rm, __shfl_xor_sync(0xffffffffu, rm, off, 16));
            float mn = fmaxf(m[i], rm);
            alpha[i] = __expf(m[i] - mn);
            m[i] = mn;
            float rs = 0.f;
#pragma unroll
            for (int j = 0; j < 4; j++) {
                p[i][j] = __expf(s[i][j] - mn);
                rs += p[i][j];
            }
#pragma unroll
            for (int off = 8; off >= 1; off >>= 1)
                rs += __shfl_xor_sync(0xffffffffu, rs, off, 16);
            l[i] = l[i] * alpha[i] + rs;
#pragma unroll
            for (int j = 0; j < 4; j++) acc[i][j] *= alpha[i];
        }

        __syncthreads();

#pragma unroll
        for (int j = 0; j < 4; j++)
#pragma unroll
            for (int i = 0; i < 4; i++)
                Kt[tx * 4 + j][ty * 4 + i] = p[i][j];
        __syncthreads();

#pragma unroll 4
        for (int k = 0; k < 64; k++) {
            float4 p4 = *(const float4*)&Kt[k][ty * 4];
            float4 v4 = *(const float4*)&Vs[k][tx * 4];
            float pa[4] = {p4.x, p4.y, p4.z, p4.w};
            float vb[4] = {v4.x, v4.y, v4.z, v4.w};
#pragma unroll
            for (int i = 0; i < 4; i++)
#pragma unroll
                for (int j = 0; j < 4; j++)
                    acc[i][j] = fmaf(pa[i], vb[j], acc[i][j]);
        }
        __syncthreads();
    }

    // Normalize; write ctx directly as hi/lo bf16 for the dense GEMM
#pragma unroll
    for (int i = 0; i < 4; i++) {
        float inv = 1.f / l[i];
        float v0 = acc[i][0] * inv, v1 = acc[i][1] * inv;
        float v2 = acc[i][2] * inv, v3 = acc[i][3] * inv;
        __nv_bfloat162 h01 = __floats2bfloat162_rn(v0, v1);
        __nv_bfloat162 h23 = __floats2bfloat162_rn(v2, v3);
        __nv_bfloat162 l01 = __floats2bfloat162_rn(v0 - __bfloat162float(h01.x),
                                                   v1 - __bfloat162float(h01.y));
        __nv_bfloat162 l23 = __floats2bfloat162_rn(v2 - __bfloat162float(h23.x),
                                                   v3 - __bfloat162float(h23.y));
        size_t idx = (rowbase + q0 + ty * 4 + i) * HIDDEN + h * HD + tx * 4;
        *(uint2*)&ctx_hi[idx] = make_uint2(*(uint32_t*)&h01, *(uint32_t*)&h23);
        *(uint2*)&ctx_lo[idx] = make_uint2(*(uint32_t*)&l01, *(uint32_t*)&l23);
    }
}

// ---------------------------------------------------------------------------
extern "C" void kernel_launch(void* const* d_in, const int* in_sizes, int n_in,
                              void* d_out, int out_size)
{
    const float* x       = (const float*)d_in[0];
    const float* w_qkv   = (const float*)d_in[1];
    const float* w_dense = (const float*)d_in[2];
    float* out           = (float*)d_out;

    float* qkv;
    __nv_bfloat16 *xh, *xl, *wqh, *wql, *wdh, *wdl, *ch, *cl;
    cudaGetSymbolAddress((void**)&qkv, g_qkv);
    cudaGetSymbolAddress((void**)&xh, g_x_hi);   cudaGetSymbolAddress((void**)&xl, g_x_lo);
    cudaGetSymbolAddress((void**)&wqh, g_wq_hi); cudaGetSymbolAddress((void**)&wql, g_wq_lo);
    cudaGetSymbolAddress((void**)&wdh, g_wd_hi); cudaGetSymbolAddress((void**)&wdl, g_wd_lo);
    cudaGetSymbolAddress((void**)&ch, g_ctx_hi); cudaGetSymbolAddress((void**)&cl, g_ctx_lo);

    cudaFuncSetAttribute(gemm_bf16, cudaFuncAttributeMaxDynamicSharedMemorySize,
                         GSMEM_B);
    cudaFuncSetAttribute(attn_kernel, cudaFuncAttributeMaxDynamicSharedMemorySize,
                         ASMEM_BYTES);

    // 0) fp32 -> hi/lo bf16 conversions
    {
        int n4;
        n4 = BTOK * HIDDEN / 4;
        cvt_hilo<<<(n4 + 255) / 256, 256>>>(x, xh, xl, n4);
        n4 = QKVCOLS * HIDDEN / 4;
        cvt_hilo<<<(n4 + 255) / 256, 256>>>(w_qkv, wqh, wql, n4);
        n4 = HIDDEN * HIDDEN / 4;
        cvt_hilo<<<(n4 + 255) / 256, 256>>>(w_dense, wdh, wdl, n4);
    }

    // 1) QKV projection (tensor cores): g_qkv = x @ w_qkv^T
    {
        dim3 grid(QKVCOLS / 128, BTOK / 128);
        gemm_bf16<<<grid, 256, GSMEM_B>>>(xh, xl, wqh, wql, qkv, QKVCOLS, HIDDEN);
    }

    // 2) Attention -> ctx (hi/lo bf16)
    {
        dim3 grid(SEQ / 64, BATCH * NH);
        attn_kernel<<<grid, 256, ASMEM_BYTES>>>(qkv, ch, cl);
    }

    // 3) Output dense (tensor cores): out = ctx @ w_dense^T
    {
        dim3 grid(HIDDEN / 128, BTOK / 128);
        gemm_bf16<<<grid, 256, GSMEM_B>>>(ch, cl, wdh, wdl, out, HIDDEN, HIDDEN);
    }
}

// round 6
// speedup vs baseline: 2.2872x; 1.8939x over previous
#include <cuda_runtime.h>
#include <cuda_bf16.h>
#include <math.h>
#include <stdint.h>

#define HIDDEN  1024
#define NH      16
#define HD      64
#define SEQ     2048
#define BATCH   2
#define BTOK    (BATCH * SEQ)      // 4096
#define QKVCOLS (3 * HIDDEN)       // 3072
#define NBH     (BATCH * NH)       // 32

// ---------------------------------------------------------------------------
// Device-global scratch
// ---------------------------------------------------------------------------
__device__ float g_qkv[(size_t)BTOK * QKVCOLS];

__device__ __nv_bfloat16 g_x_hi[(size_t)BTOK * HIDDEN];
__device__ __nv_bfloat16 g_x_lo[(size_t)BTOK * HIDDEN];
__device__ __nv_bfloat16 g_wq_hi[(size_t)QKVCOLS * HIDDEN];
__device__ __nv_bfloat16 g_wq_lo[(size_t)QKVCOLS * HIDDEN];
__device__ __nv_bfloat16 g_wd_hi[(size_t)HIDDEN * HIDDEN];
__device__ __nv_bfloat16 g_wd_lo[(size_t)HIDDEN * HIDDEN];
__device__ __nv_bfloat16 g_ctx_hi[(size_t)BTOK * HIDDEN];
__device__ __nv_bfloat16 g_ctx_lo[(size_t)BTOK * HIDDEN];

// per-head layouts for attention
__device__ __nv_bfloat16 g_q_hi[(size_t)NBH * SEQ * HD];
__device__ __nv_bfloat16 g_q_lo[(size_t)NBH * SEQ * HD];
__device__ __nv_bfloat16 g_k_hi[(size_t)NBH * SEQ * HD];
__device__ __nv_bfloat16 g_k_lo[(size_t)NBH * SEQ * HD];
__device__ __nv_bfloat16 g_vt_hi[(size_t)NBH * HD * SEQ];   // [bh][d][s]
__device__ __nv_bfloat16 g_vt_lo[(size_t)NBH * HD * SEQ];

// ---------------------------------------------------------------------------
// PTX wrappers (sm_80-class, legal on compute_103)
// ---------------------------------------------------------------------------
__device__ __forceinline__ uint32_t smem_u32(const void* p) {
    uint32_t a;
    asm("{ .reg .u64 t; cvta.to.shared.u64 t, %1; cvt.u32.u64 %0, t; }"
        : "=r"(a) : "l"(p));
    return a;
}

__device__ __forceinline__ void ldm_x4(uint32_t* r, uint32_t addr) {
    asm volatile("ldmatrix.sync.aligned.m8n8.x4.shared.b16 {%0,%1,%2,%3}, [%4];"
                 : "=r"(r[0]), "=r"(r[1]), "=r"(r[2]), "=r"(r[3]) : "r"(addr));
}

__device__ __forceinline__ void mma16816(float* d, const uint32_t* a,
                                         uint32_t b0, uint32_t b1) {
    asm volatile(
        "mma.sync.aligned.m16n8k16.row.col.f32.bf16.bf16.f32 "
        "{%0,%1,%2,%3}, {%4,%5,%6,%7}, {%8,%9}, {%0,%1,%2,%3};"
        : "+f"(d[0]), "+f"(d[1]), "+f"(d[2]), "+f"(d[3])
        : "r"(a[0]), "r"(a[1]), "r"(a[2]), "r"(a[3]), "r"(b0), "r"(b1));
}

__device__ __forceinline__ void cp_async16(uint32_t dst, const void* src) {
    asm volatile("cp.async.cg.shared.global [%0], [%1], 16;"
                 :: "r"(dst), "l"(src));
}
#define CP_COMMIT() asm volatile("cp.async.commit_group;")
#define CP_WAIT(N)  asm volatile("cp.async.wait_group %0;" :: "n"(N))

__device__ __forceinline__ uint32_t pack_hi(float x, float y) {
    __nv_bfloat162 h = __floats2bfloat162_rn(x, y);
    return *(uint32_t*)&h;
}
__device__ __forceinline__ uint32_t pack_lo(float x, float y, uint32_t hi) {
    __nv_bfloat162 h = *(__nv_bfloat162*)&hi;
    __nv_bfloat162 l = __floats2bfloat162_rn(x - __bfloat162float(h.x),
                                             y - __bfloat162float(h.y));
    return *(uint32_t*)&l;
}

// ---------------------------------------------------------------------------
// fp32 -> (bf16 hi, bf16 lo)
// ---------------------------------------------------------------------------
__global__ void cvt_hilo(const float* __restrict__ in,
                         __nv_bfloat16* __restrict__ hi,
                         __nv_bfloat16* __restrict__ lo, int n4)
{
    int i = blockIdx.x * blockDim.x + threadIdx.x;
    if (i >= n4) return;
    float4 v = *(const float4*)&in[i * 4];
    uint32_t h01 = pack_hi(v.x, v.y), h23 = pack_hi(v.z, v.w);
    uint32_t l01 = pack_lo(v.x, v.y, h01), l23 = pack_lo(v.z, v.w, h23);
    *(uint2*)&hi[i * 4] = make_uint2(h01, h23);
    *(uint2*)&lo[i * 4] = make_uint2(l01, l23);
}

// ---------------------------------------------------------------------------
// Split g_qkv (fp32) into per-head Q,K (row-major) and V^T (d-major) hi/lo bf16
// grid (SEQ/64, NBH), block 256
// ---------------------------------------------------------------------------
__global__ void qkv_split(const float* __restrict__ qkv,
                          __nv_bfloat16* __restrict__ qh, __nv_bfloat16* __restrict__ ql,
                          __nv_bfloat16* __restrict__ kh, __nv_bfloat16* __restrict__ kl,
                          __nv_bfloat16* __restrict__ vth, __nv_bfloat16* __restrict__ vtl)
{
    __shared__ uint16_t sh[64][72];
    __shared__ uint16_t sl[64][72];
    const int tid = threadIdx.x;
    const int s0 = blockIdx.x * 64;
    const int bh = blockIdx.y;
    const int b = bh >> 4, h = bh & 15;
    const size_t srow = (size_t)b * SEQ + s0;
    const size_t drow = (size_t)bh * SEQ + s0;

#pragma unroll
    for (int i = 0; i < 4; i++) {
        int id = tid + i * 256;           // 0..1023
        int r = id >> 4;
        int c = (id & 15) << 2;
        const float* src = &qkv[(srow + r) * QKVCOLS + h * HD + c];
        // Q
        {
            float4 v = *(const float4*)src;
            uint32_t h01 = pack_hi(v.x, v.y), h23 = pack_hi(v.z, v.w);
            uint32_t l01 = pack_lo(v.x, v.y, h01), l23 = pack_lo(v.z, v.w, h23);
            *(uint2*)&qh[(drow + r) * HD + c] = make_uint2(h01, h23);
            *(uint2*)&ql[(drow + r) * HD + c] = make_uint2(l01, l23);
        }
        // K
        {
            float4 v = *(const float4*)(src + HIDDEN);
            uint32_t h01 = pack_hi(v.x, v.y), h23 = pack_hi(v.z, v.w);
            uint32_t l01 = pack_lo(v.x, v.y, h01), l23 = pack_lo(v.z, v.w, h23);
            *(uint2*)&kh[(drow + r) * HD + c] = make_uint2(h01, h23);
            *(uint2*)&kl[(drow + r) * HD + c] = make_uint2(l01, l23);
        }
        // V -> transposed staging in smem
        {
            float4 v = *(const float4*)(src + 2 * HIDDEN);
            float vv[4] = {v.x, v.y, v.z, v.w};
#pragma unroll
            for (int t = 0; t < 4; t++) {
                __nv_bfloat16 hb = __float2bfloat16_rn(vv[t]);
                __nv_bfloat16 lb = __float2bfloat16_rn(vv[t] - __bfloat162float(hb));
                sh[c + t][r] = *(uint16_t*)&hb;
                sl[c + t][r] = *(uint16_t*)&lb;
            }
        }
    }
    __syncthreads();

    const size_t vbase = (size_t)bh * HD * SEQ + s0;
#pragma unroll
    for (int i = 0; i < 2; i++) {
        int id = tid + i * 256;           // 0..511
        int d = id >> 3;
        int c8 = (id & 7) << 3;
        *(uint4*)&vth[vbase + (size_t)d * SEQ + c8] = *(uint4*)&sh[d][c8];
        *(uint4*)&vtl[vbase + (size_t)d * SEQ + c8] = *(uint4*)&sl[d][c8];
    }
}

// ===========================================================================
// bf16 split-precision GEMM (BK=32, double-buffered -> 80KB smem -> 2 CTA/SM)
// C[M,N] = A[M,K] @ B[N,K]^T, tile 128x128, 8 warps (2m x 4n, warp 64x32)
// ===========================================================================
#define STRD 40
#define ATILE_B (128 * STRD * 2)      // 10240
#define GBUF_B  (4 * ATILE_B)         // 40960
#define GSMEM_B (2 * GBUF_B)          // 81920

__global__ __launch_bounds__(256, 2)
void gemm_bf16(const __nv_bfloat16* __restrict__ Ahi,
               const __nv_bfloat16* __restrict__ Alo,
               const __nv_bfloat16* __restrict__ Bhi,
               const __nv_bfloat16* __restrict__ Blo,
               float* __restrict__ C, int N, int K)
{
    extern __shared__ char sm[];
    const uint32_t smb = smem_u32(sm);
    const int tid = threadIdx.x;
    const int wid = tid >> 5;
    const int lane = tid & 31;
    const int wm = wid & 1;
    const int wn = wid >> 1;
    const int n0 = blockIdx.x * 128;
    const int m0 = blockIdx.y * 128;

    const int cr = tid >> 1;                  // row 0..127
    const int cc = (tid & 1) << 4;            // element col 0 or 16
    const size_t gA = (size_t)(m0 + cr) * K + cc;
    const size_t gB = (size_t)(n0 + cr) * K + cc;
    const uint32_t sRow = (uint32_t)(cr * STRD + cc) * 2;

    float acc[4][4][4];
#pragma unroll
    for (int i = 0; i < 4; i++)
#pragma unroll
        for (int j = 0; j < 4; j++)
#pragma unroll
            for (int f = 0; f < 4; f++) acc[i][j][f] = 0.f;

    const uint32_t aoff = ((wm * 64 + (lane & 15)) * STRD + ((lane >> 4) << 3)) * 2;
    const uint32_t boff = ((wn * 32 + (lane & 15)) * STRD + ((lane >> 4) << 3)) * 2;

    const int nch = K >> 5;

    auto issue = [&](int buf, int k0) {
        uint32_t base = smb + buf * GBUF_B;
#pragma unroll
        for (int q = 0; q < 2; q++) {
            uint32_t so = sRow + q * 16;
            int go = k0 + q * 8;
            cp_async16(base + 0 * ATILE_B + so, Ahi + gA + go);
            cp_async16(base + 1 * ATILE_B + so, Alo + gA + go);
            cp_async16(base + 2 * ATILE_B + so, Bhi + gB + go);
            cp_async16(base + 3 * ATILE_B + so, Blo + gB + go);
        }
        CP_COMMIT();
    };

    issue(0, 0);

    for (int ch = 0; ch < nch; ch++) {
        const int buf = ch & 1;
        if (ch + 1 < nch) { issue(1 - buf, (ch + 1) << 5); CP_WAIT(1); }
        else              { CP_WAIT(0); }
        __syncthreads();

        const uint32_t tAhi = smb + buf * GBUF_B;
        const uint32_t tAlo = tAhi + ATILE_B;
        const uint32_t tBhi = tAhi + 2 * ATILE_B;
        const uint32_t tBlo = tAhi + 3 * ATILE_B;

#pragma unroll
        for (int kk = 0; kk < 2; kk++) {
            const uint32_t ko = kk * 32;
            uint32_t ah[4][4], bh[2][4];
#pragma unroll
            for (int mi = 0; mi < 4; mi++)
                ldm_x4(ah[mi], tAhi + aoff + mi * (16 * STRD * 2) + ko);
#pragma unroll
            for (int nt = 0; nt < 2; nt++)
                ldm_x4(bh[nt], tBhi + boff + nt * (16 * STRD * 2) + ko);
#pragma unroll
            for (int mi = 0; mi < 4; mi++)
#pragma unroll
                for (int nt = 0; nt < 2; nt++)
#pragma unroll
                    for (int h = 0; h < 2; h++)
                        mma16816(acc[mi][nt * 2 + h], ah[mi], bh[nt][h], bh[nt][h + 2]);
            {
                uint32_t bl[2][4];
#pragma unroll
                for (int nt = 0; nt < 2; nt++)
                    ldm_x4(bl[nt], tBlo + boff + nt * (16 * STRD * 2) + ko);
#pragma unroll
                for (int mi = 0; mi < 4; mi++)
#pragma unroll
                    for (int nt = 0; nt < 2; nt++)
#pragma unroll
                        for (int h = 0; h < 2; h++)
                            mma16816(acc[mi][nt * 2 + h], ah[mi], bl[nt][h], bl[nt][h + 2]);
            }
            {
                uint32_t al[4][4];
#pragma unroll
                for (int mi = 0; mi < 4; mi++)
                    ldm_x4(al[mi], tAlo + aoff + mi * (16 * STRD * 2) + ko);
#pragma unroll
                for (int mi = 0; mi < 4; mi++)
#pragma unroll
                    for (int nt = 0; nt < 2; nt++)
#pragma unroll
                        for (int h = 0; h < 2; h++)
                            mma16816(acc[mi][nt * 2 + h], al[mi], bh[nt][h], bh[nt][h + 2]);
            }
        }
        __syncthreads();
    }

    const int mrow = m0 + wm * 64 + (lane >> 2);
    const int ncol = n0 + wn * 32 + (lane & 3) * 2;
#pragma unroll
    for (int mi = 0; mi < 4; mi++)
#pragma unroll
        for (int nj = 0; nj < 4; nj++) {
            float* d = acc[mi][nj];
            size_t r0 = (size_t)(mrow + mi * 16) * N + ncol + nj * 8;
            size_t r1 = r0 + 8 * (size_t)N;
            *(float2*)&C[r0] = make_float2(d[0], d[1]);
            *(float2*)&C[r1] = make_float2(d[2], d[3]);
        }
}

// ===========================================================================
// Tensor-core flash attention (bf16 split, fp32 softmax)
// grid (SEQ/128, NBH), 256 threads = 8 warps, warp tile m16 x all 64 kv/hd
// ===========================================================================
#define KSTRD 72
#define KTILE_B (64 * KSTRD * 2)     // 9216
#define ABUF_B  (4 * KTILE_B)        // 36864
#define ATT_SMEM (2 * ABUF_B)        // 73728

__global__ __launch_bounds__(256, 2)
void attn_tc(const __nv_bfloat16* __restrict__ Qh, const __nv_bfloat16* __restrict__ Ql,
             const __nv_bfloat16* __restrict__ Kh, const __nv_bfloat16* __restrict__ Kl,
             const __nv_bfloat16* __restrict__ Vth, const __nv_bfloat16* __restrict__ Vtl,
             __nv_bfloat16* __restrict__ ctx_hi, __nv_bfloat16* __restrict__ ctx_lo)
{
    extern __shared__ char sm[];
    const uint32_t smb = smem_u32(sm);
    const int tid = threadIdx.x;
    const int wid = tid >> 5;
    const int lane = tid & 31;
    const int q0 = blockIdx.x * 128;
    const int bh = blockIdx.y;
    const size_t qbase = ((size_t)bh * SEQ + q0) * HD;
    const size_t kbase = (size_t)bh * SEQ * HD;
    const size_t vbase = (size_t)bh * HD * SEQ;

    // ---- Stage Q tile (128x64 hi/lo) into smem, load A fragments ----
#pragma unroll
    for (int p = 0; p < 4; p++) {
        int id = tid + p * 256;               // 0..1023
        int r = id >> 3;
        int c = (id & 7) << 3;
        uint32_t so = (uint32_t)(r * KSTRD + c) * 2;
        cp_async16(smb + so, Qh + qbase + r * HD + c);
        cp_async16(smb + (128 * KSTRD * 2) + so, Ql + qbase + r * HD + c);
    }
    CP_COMMIT(); CP_WAIT(0);
    __syncthreads();

    uint32_t qhf[4][4], qlf[4][4];
    const uint32_t qoff = ((wid * 16 + (lane & 15)) * KSTRD + ((lane >> 4) << 3)) * 2;
#pragma unroll
    for (int ks = 0; ks < 4; ks++) {
        ldm_x4(qhf[ks], smb + qoff + ks * 32);
        ldm_x4(qlf[ks], smb + (128 * KSTRD * 2) + qoff + ks * 32);
    }
    __syncthreads();   // smem now free for KV double buffer

    // ---- KV streaming ----
    auto kv_issue = [&](int buf, int kv0) {
        uint32_t base = smb + buf * ABUF_B;
#pragma unroll
        for (int p = 0; p < 2; p++) {
            int id = tid + p * 256;           // 0..511
            int r = id >> 3;
            int c = (id & 7) << 3;
            uint32_t so = (uint32_t)(r * KSTRD + c) * 2;
            size_t kg = kbase + (size_t)(kv0 + r) * HD + c;
            cp_async16(base + 0 * KTILE_B + so, Kh + kg);
            cp_async16(base + 1 * KTILE_B + so, Kl + kg);
            size_t vg = vbase + (size_t)r * SEQ + kv0 + c;
            cp_async16(base + 2 * KTILE_B + so, Vth + vg);
            cp_async16(base + 3 * KTILE_B + so, Vtl + vg);
        }
        CP_COMMIT();
    };

    float oacc[8][4];
#pragma unroll
    for (int j = 0; j < 8; j++)
#pragma unroll
        for (int f = 0; f < 4; f++) oacc[j][f] = 0.f;
    float mrow0 = -1e30f, mrow1 = -1e30f, lrow0 = 0.f, lrow1 = 0.f;

    const uint32_t frow = ((lane & 15) * KSTRD + ((lane >> 4) << 3)) * 2;
    const float scale = 0.125f;

    kv_issue(0, 0);

    for (int ch = 0; ch < SEQ / 64; ch++) {
        const int buf = ch & 1;
        if (ch + 1 < SEQ / 64) { kv_issue(1 - buf, (ch + 1) * 64); CP_WAIT(1); }
        else                   { CP_WAIT(0); }
        __syncthreads();

        const uint32_t tKh = smb + buf * ABUF_B;
        const uint32_t tKl = tKh + KTILE_B;
        const uint32_t tVh = tKh + 2 * KTILE_B;
        const uint32_t tVl = tKh + 3 * KTILE_B;

        // ---- S = Q @ K^T (3-term split) ----
        float s[8][4];
#pragma unroll
        for (int j = 0; j < 8; j++)
#pragma unroll
            for (int f = 0; f < 4; f++) s[j][f] = 0.f;

#pragma unroll
        for (int ks = 0; ks < 4; ks++) {
            const uint32_t ko = ks * 32;
#pragma unroll
            for (int g = 0; g < 4; g++) {
                uint32_t bf[4];
                ldm_x4(bf, tKh + frow + g * (16 * KSTRD * 2) + ko);
#pragma unroll
                for (int h = 0; h < 2; h++) {
                    mma16816(s[2 * g + h], qhf[ks], bf[h], bf[h + 2]);
                    mma16816(s[2 * g + h], qlf[ks], bf[h], bf[h + 2]);
                }
            }
#pragma unroll
            for (int g = 0; g < 4; g++) {
                uint32_t bf[4];
                ldm_x4(bf, tKl + frow + g * (16 * KSTRD * 2) + ko);
#pragma unroll
                for (int h = 0; h < 2; h++)
                    mma16816(s[2 * g + h], qhf[ks], bf[h], bf[h + 2]);
            }
        }

        // ---- online softmax (rows: r=lane>>2 and r+8) ----
        float rm0 = -1e30f, rm1 = -1e30f;
#pragma unroll
        for (int j = 0; j < 8; j++) {
            s[j][0] *= scale; s[j][1] *= scale; s[j][2] *= scale; s[j][3] *= scale;
            rm0 = fmaxf(rm0, fmaxf(s[j][0], s[j][1]));
            rm1 = fmaxf(rm1, fmaxf(s[j][2], s[j][3]));
        }
#pragma unroll
        for (int off = 1; off <= 2; off <<= 1) {
            rm0 = fmaxf(rm0, __shfl_xor_sync(0xffffffffu, rm0, off));
            rm1 = fmaxf(rm1, __shfl_xor_sync(0xffffffffu, rm1, off));
        }
        float mn0 = fmaxf(mrow0, rm0), mn1 = fmaxf(mrow1, rm1);
        float a0 = __expf(mrow0 - mn0), a1 = __expf(mrow1 - mn1);
        mrow0 = mn0; mrow1 = mn1;
        float rs0 = 0.f, rs1 = 0.f;
#pragma unroll
        for (int j = 0; j < 8; j++) {
            s[j][0] = __expf(s[j][0] - mn0); rs0 += s[j][0];
            s[j][1] = __expf(s[j][1] - mn0); rs0 += s[j][1];
            s[j][2] = __expf(s[j][2] - mn1); rs1 += s[j][2];
            s[j][3] = __expf(s[j][3] - mn1); rs1 += s[j][3];
        }
#pragma unroll
        for (int off = 1; off <= 2; off <<= 1) {
            rs0 += __shfl_xor_sync(0xffffffffu, rs0, off);
            rs1 += __shfl_xor_sync(0xffffffffu, rs1, off);
        }
        lrow0 = lrow0 * a0 + rs0;
        lrow1 = lrow1 * a1 + rs1;
#pragma unroll
        for (int j = 0; j < 8; j++) {
            oacc[j][0] *= a0; oacc[j][1] *= a0;
            oacc[j][2] *= a1; oacc[j][3] *= a1;
        }

        // ---- O += P @ V (3-term split, P in registers) ----
#pragma unroll
        for (int kc = 0; kc < 4; kc++) {
            uint32_t pa_h[4], pa_l[4];
            pa_h[0] = pack_hi(s[2 * kc][0], s[2 * kc][1]);
            pa_l[0] = pack_lo(s[2 * kc][0], s[2 * kc][1], pa_h[0]);
            pa_h[1] = pack_hi(s[2 * kc][2], s[2 * kc][3]);
            pa_l[1] = pack_lo(s[2 * kc][2], s[2 * kc][3], pa_h[1]);
            pa_h[2] = pack_hi(s[2 * kc + 1][0], s[2 * kc + 1][1]);
            pa_l[2] = pack_lo(s[2 * kc + 1][0], s[2 * kc + 1][1], pa_h[2]);
            pa_h[3] = pack_hi(s[2 * kc + 1][2], s[2 * kc + 1][3]);
            pa_l[3] = pack_lo(s[2 * kc + 1][2], s[2 * kc + 1][3], pa_h[3]);

            const uint32_t ko = kc * 32;
#pragma unroll
            for (int g = 0; g < 4; g++) {
                uint32_t vf[4];
                ldm_x4(vf, tVh + frow + g * (16 * KSTRD * 2) + ko);
#pragma unroll
                for (int h = 0; h < 2; h++) {
                    mma16816(oacc[2 * g + h], pa_h, vf[h], vf[h + 2]);
                    mma16816(oacc[2 * g + h], pa_l, vf[h], vf[h + 2]);
                }
            }
#pragma unroll
            for (int g = 0; g < 4; g++) {
                uint32_t vf[4];
                ldm_x4(vf, tVl + frow + g * (16 * KSTRD * 2) + ko);
#pragma unroll
                for (int h = 0; h < 2; h++)
                    mma16816(oacc[2 * g + h], pa_h, vf[h], vf[h + 2]);
            }
        }
        __syncthreads();   // everyone done with buf before it is refilled
    }

    // ---- epilogue: ctx hi/lo bf16 ----
    const int b = bh >> 4, h = bh & 15;
    const float inv0 = 1.f / lrow0, inv1 = 1.f / lrow1;
    const size_t row0 = (size_t)b * SEQ + q0 + wid * 16 + (lane >> 2);
    const size_t row1 = row0 + 8;
#pragma unroll
    for (int j = 0; j < 8; j++) {
        int col = h * HD + j * 8 + 2 * (lane & 3);
        float v0 = oacc[j][0] * inv0, v1 = oacc[j][1] * inv0;
        float v2 = oacc[j][2] * inv1, v3 = oacc[j][3] * inv1;
        uint32_t h01 = pack_hi(v0, v1), h23 = pack_hi(v2, v3);
        uint32_t l01 = pack_lo(v0, v1, h01), l23 = pack_lo(v2, v3, h23);
        *(uint32_t*)&ctx_hi[row0 * HIDDEN + col] = h01;
        *(uint32_t*)&ctx_lo[row0 * HIDDEN + col] = l01;
        *(uint32_t*)&ctx_hi[row1 * HIDDEN + col] = h23;
        *(uint32_t*)&ctx_lo[row1 * HIDDEN + col] = l23;
    }
}

// ---------------------------------------------------------------------------
extern "C" void kernel_launch(void* const* d_in, const int* in_sizes, int n_in,
                              void* d_out, int out_size)
{
    const float* x       = (const float*)d_in[0];
    const float* w_qkv   = (const float*)d_in[1];
    const float* w_dense = (const float*)d_in[2];
    float* out           = (float*)d_out;

    float* qkv;
    __nv_bfloat16 *xh, *xl, *wqh, *wql, *wdh, *wdl, *ch, *cl;
    __nv_bfloat16 *q_h, *q_l, *k_h, *k_l, *vt_h, *vt_l;
    cudaGetSymbolAddress((void**)&qkv, g_qkv);
    cudaGetSymbolAddress((void**)&xh, g_x_hi);   cudaGetSymbolAddress((void**)&xl, g_x_lo);
    cudaGetSymbolAddress((void**)&wqh, g_wq_hi); cudaGetSymbolAddress((void**)&wql, g_wq_lo);
    cudaGetSymbolAddress((void**)&wdh, g_wd_hi); cudaGetSymbolAddress((void**)&wdl, g_wd_lo);
    cudaGetSymbolAddress((void**)&ch, g_ctx_hi); cudaGetSymbolAddress((void**)&cl, g_ctx_lo);
    cudaGetSymbolAddress((void**)&q_h, g_q_hi);  cudaGetSymbolAddress((void**)&q_l, g_q_lo);
    cudaGetSymbolAddress((void**)&k_h, g_k_hi);  cudaGetSymbolAddress((void**)&k_l, g_k_lo);
    cudaGetSymbolAddress((void**)&vt_h, g_vt_hi); cudaGetSymbolAddress((void**)&vt_l, g_vt_lo);

    cudaFuncSetAttribute(gemm_bf16, cudaFuncAttributeMaxDynamicSharedMemorySize, GSMEM_B);
    cudaFuncSetAttribute(attn_tc, cudaFuncAttributeMaxDynamicSharedMemorySize, ATT_SMEM);

    // 0) operand conversions
    {
        int n4 = BTOK * HIDDEN / 4;
        cvt_hilo<<<(n4 + 255) / 256, 256>>>(x, xh, xl, n4);
        n4 = QKVCOLS * HIDDEN / 4;
        cvt_hilo<<<(n4 + 255) / 256, 256>>>(w_qkv, wqh, wql, n4);
        n4 = HIDDEN * HIDDEN / 4;
        cvt_hilo<<<(n4 + 255) / 256, 256>>>(w_dense, wdh, wdl, n4);
    }

    // 1) QKV projection (tensor cores)
    {
        dim3 grid(QKVCOLS / 128, BTOK / 128);
        gemm_bf16<<<grid, 256, GSMEM_B>>>(xh, xl, wqh, wql, qkv, QKVCOLS, HIDDEN);
    }

    // 2) split into per-head bf16 hi/lo Q, K, V^T
    {
        dim3 grid(SEQ / 64, NBH);
        qkv_split<<<grid, 256>>>(qkv, q_h, q_l, k_h, k_l, vt_h, vt_l);
    }

    // 3) attention (tensor cores) -> ctx hi/lo
    {
        dim3 grid(SEQ / 128, NBH);
        attn_tc<<<grid, 256, ATT_SMEM>>>(q_h, q_l, k_h, k_l, vt_h, vt_l, ch, cl);
    }

    // 4) output dense (tensor cores)
    {
        dim3 grid(HIDDEN / 128, BTOK / 128);
        gemm_bf16<<<grid, 256, GSMEM_B>>>(ch, cl, wdh, wdl, out, HIDDEN, HIDDEN);
    }
}